// round 12
// baseline (speedup 1.0000x reference)
#include <cuda_runtime.h>
#include <cuda_bf16.h>
#include <math.h>
#include <stdint.h>

// Problem constants
#define B_  4
#define S_  2048
#define D_  1024
#define H_  16
#define HD_ 64
#define M_  (B_ * S_)

// ---------------------------------------------------------------------------
// Scratch (device globals)
// ---------------------------------------------------------------------------
__device__ __nv_bfloat16 g_Qhi[B_ * H_ * S_ * HD_];
__device__ __nv_bfloat16 g_Qlo[B_ * H_ * S_ * HD_];
__device__ __nv_bfloat16 g_Khi[B_ * H_ * S_ * HD_];
__device__ __nv_bfloat16 g_Klo[B_ * H_ * S_ * HD_];
__device__ __nv_bfloat16 g_Vhi[B_ * H_ * S_ * HD_];
__device__ __nv_bfloat16 g_Vlo[B_ * H_ * S_ * HD_];

__device__ __nv_bfloat16 g_xhi[M_ * D_];
__device__ __nv_bfloat16 g_xlo[M_ * D_];
__device__ __nv_bfloat16 g_Whi[4 * D_ * D_];
__device__ __nv_bfloat16 g_Wlo[4 * D_ * D_];

// ---------------------------------------------------------------------------
// PTX helpers (base ISA only)
// ---------------------------------------------------------------------------
__device__ __forceinline__ uint32_t smem_u32(const void* p) {
    uint32_t a;
    asm("{ .reg .u64 t; cvta.to.shared.u64 t, %1; cvt.u32.u64 %0, t; }"
        : "=r"(a) : "l"(p));
    return a;
}

__device__ __forceinline__ void cp16(uint32_t dst, const void* src) {
    asm volatile("cp.async.cg.shared.global [%0], [%1], 16;"
                 :: "r"(dst), "l"(src));
}
#define CP_COMMIT() asm volatile("cp.async.commit_group;" ::: "memory")
template <int N>
__device__ __forceinline__ void cp_wait() {
    asm volatile("cp.async.wait_group %0;" :: "n"(N) : "memory");
}

__device__ __forceinline__ void ldm_x4(uint32_t& r0, uint32_t& r1,
                                       uint32_t& r2, uint32_t& r3, uint32_t addr) {
    asm volatile("ldmatrix.sync.aligned.m8n8.x4.shared.b16 {%0,%1,%2,%3}, [%4];"
                 : "=r"(r0), "=r"(r1), "=r"(r2), "=r"(r3) : "r"(addr));
}
__device__ __forceinline__ void ldm_x4_t(uint32_t& r0, uint32_t& r1,
                                         uint32_t& r2, uint32_t& r3, uint32_t addr) {
    asm volatile("ldmatrix.sync.aligned.m8n8.x4.trans.shared.b16 {%0,%1,%2,%3}, [%4];"
                 : "=r"(r0), "=r"(r1), "=r"(r2), "=r"(r3) : "r"(addr));
}

__device__ __forceinline__ void mma_bf16(float* d, uint32_t a0, uint32_t a1,
                                         uint32_t a2, uint32_t a3,
                                         uint32_t b0, uint32_t b1) {
    asm volatile(
        "mma.sync.aligned.m16n8k16.row.col.f32.bf16.bf16.f32 "
        "{%0,%1,%2,%3}, {%4,%5,%6,%7}, {%8,%9}, {%0,%1,%2,%3};"
        : "+f"(d[0]), "+f"(d[1]), "+f"(d[2]), "+f"(d[3])
        : "r"(a0), "r"(a1), "r"(a2), "r"(a3), "r"(b0), "r"(b1));
}

__device__ __forceinline__ void split2(float x, float y, uint32_t& hi, uint32_t& lo) {
    __nv_bfloat162 h = __floats2bfloat162_rn(x, y);
    float hx = __low2float(h), hy = __high2float(h);
    __nv_bfloat162 l = __floats2bfloat162_rn(x - hx, y - hy);
    hi = *reinterpret_cast<uint32_t*>(&h);
    lo = *reinterpret_cast<uint32_t*>(&l);
}

// ---------------------------------------------------------------------------
// split kernels
// ---------------------------------------------------------------------------
__global__ void split_kernel(const float* __restrict__ src,
                             __nv_bfloat16* __restrict__ hi,
                             __nv_bfloat16* __restrict__ lo, int n4)
{
    int i = blockIdx.x * blockDim.x + threadIdx.x;
    if (i >= n4) return;
    float4 v = reinterpret_cast<const float4*>(src)[i];
    uint32_t h0, l0, h1, l1;
    split2(v.x, v.y, h0, l0);
    split2(v.z, v.w, h1, l1);
    uint32_t* hp = reinterpret_cast<uint32_t*>(hi);
    uint32_t* lp = reinterpret_cast<uint32_t*>(lo);
    hp[2 * i] = h0; hp[2 * i + 1] = h1;
    lp[2 * i] = l0; lp[2 * i + 1] = l1;
}

__global__ void wsplit_kernel(const float* __restrict__ w0, const float* __restrict__ w1,
                              const float* __restrict__ w2, const float* __restrict__ w3,
                              __nv_bfloat16* __restrict__ hi,
                              __nv_bfloat16* __restrict__ lo)
{
    int i = blockIdx.x * blockDim.x + threadIdx.x;
    int wsel = blockIdx.y;
    const float* src = (wsel == 0) ? w0 : (wsel == 1) ? w1 : (wsel == 2) ? w2 : w3;
    size_t off = (size_t)wsel * (D_ * D_ / 4);
    float4 v = reinterpret_cast<const float4*>(src)[i];
    uint32_t h0, l0, h1, l1;
    split2(v.x, v.y, h0, l0);
    split2(v.z, v.w, h1, l1);
    uint32_t* hp = reinterpret_cast<uint32_t*>(hi) + 2 * off;
    uint32_t* lp = reinterpret_cast<uint32_t*>(lo) + 2 * off;
    hp[2 * i] = h0; hp[2 * i + 1] = h1;
    lp[2 * i] = l0; lp[2 * i + 1] = l1;
}

// ---------------------------------------------------------------------------
// mma.sync GEMM v2: CTA 256x128, warp tile 64x64 (8 warps), BK=64,
// 3-stage ring, 1 sync/iter, bf16-pair 3-segment (K=3072 effective).
// fused=1: QKV fused (gridDim.x=24; wsel selects W/bias/dst; RoPE for Q,K)
// fused=0: out-projection, fp32 row-major C
// ---------------------------------------------------------------------------
#define TM 256
#define TN 128
#define BK 64
#define NCH 48                    // 3 segments * 1024/64
#define GROWB 144
#define GATILE (TM * GROWB)       // 36864
#define GWTILE (TN * GROWB)       // 18432
#define GSTAGE (GATILE + GWTILE)  // 55296
#define GEMM_DYN_SMEM (3 * GSTAGE)   // 165888

__device__ __forceinline__ void load_tile(
    int tid, int m0, int n0w, uint32_t smem_base, int c, int s,
    const __nv_bfloat16* Ahi, const __nv_bfloat16* Alo,
    const __nv_bfloat16* Whi, const __nv_bfloat16* Wlo)
{
    int seg = c >> 4;                 // 0: hi*hi, 1: hi*lo, 2: lo*hi
    int kb  = (c & 15) * BK;
    const char* ap = (const char*)((seg == 2) ? Alo : Ahi);
    const char* bp = (const char*)((seg == 1) ? Wlo : Whi);
    uint32_t abase = smem_base + s * GSTAGE;
    uint32_t wbase = abase + GATILE;
    // A: 256 rows, one row per thread, 8x16B
    {
        const char* arow = ap + ((size_t)(m0 + tid) * 1024 + kb) * 2;
        uint32_t d = abase + tid * GROWB;
#pragma unroll
        for (int g = 0; g < 8; g++)
            cp16(d + g * 16, arow + g * 16);
    }
    // W: 128 rows, 2 threads/row, 4x16B each
    {
        int row = tid >> 1;
        int gb  = (tid & 1) * 4;
        const char* brow = bp + ((size_t)(n0w + row) * 1024 + kb) * 2;
        uint32_t d = wbase + row * GROWB;
#pragma unroll
        for (int g = 0; g < 4; g++)
            cp16(d + (gb + g) * 16, brow + (gb + g) * 16);
    }
    CP_COMMIT();
}

__global__ void __launch_bounds__(256, 1) gemm_tc(
    const __nv_bfloat16* __restrict__ Ahi, const __nv_bfloat16* __restrict__ Alo,
    const __nv_bfloat16* __restrict__ Whi0, const __nv_bfloat16* __restrict__ Wlo0,
    const float* __restrict__ b0p, const float* __restrict__ b1p,
    const float* __restrict__ b2p, float* __restrict__ Cout,
    __nv_bfloat16* __restrict__ Qh, __nv_bfloat16* __restrict__ Ql,
    __nv_bfloat16* __restrict__ Kh, __nv_bfloat16* __restrict__ Kl,
    __nv_bfloat16* __restrict__ Vh, __nv_bfloat16* __restrict__ Vl,
    const float* __restrict__ cosp, const float* __restrict__ sinp, int fused)
{
    extern __shared__ char dyn[];
    __shared__ float bias_s[TN];

    const int tid = threadIdx.x;
    const int wid = tid >> 5;
    const int lid = tid & 31;
    const int wm  = wid >> 1;          // 0..3
    const int wn  = wid & 1;           // 0..1
    const int m0  = blockIdx.y * TM;

    int wsel, n0w;
    const __nv_bfloat16 *Wh, *Wl;
    const float* bias;
    if (fused) {
        wsel = blockIdx.x >> 3;                 // 0:Q 1:K 2:V
        n0w  = (blockIdx.x & 7) * TN;
        Wh = Whi0 + (size_t)wsel * (D_ * D_);
        Wl = Wlo0 + (size_t)wsel * (D_ * D_);
        bias = (wsel == 0) ? b0p : (wsel == 1) ? b1p : b2p;
    } else {
        wsel = -1;
        n0w  = blockIdx.x * TN;
        Wh = Whi0; Wl = Wlo0;
        bias = b0p;
    }

    uint32_t smem_base = smem_u32(dyn);
    if (tid < TN) bias_s[tid] = bias[n0w + tid];

    float acc[4][8][4];
#pragma unroll
    for (int mt = 0; mt < 4; mt++)
#pragma unroll
        for (int na = 0; na < 8; na++)
#pragma unroll
            for (int q = 0; q < 4; q++) acc[mt][na][q] = 0.f;

    load_tile(tid, m0, n0w, smem_base, 0, 0, Ahi, Alo, Wh, Wl);
    load_tile(tid, m0, n0w, smem_base, 1, 1, Ahi, Alo, Wh, Wl);

    const int a_row = ((lid >> 3) & 1) * 8 + (lid & 7);
    const int a_col = ((lid >> 4) & 1) * 8;
    const int b_row = ((lid >> 4) & 1) * 8 + (lid & 7);
    const int b_col = ((lid >> 3) & 1) * 8;

    int s_cur = 0, s_nxt = 2;
    for (int c = 0; c < NCH; c++) {
        if (c >= NCH - 2) cp_wait<0>(); else cp_wait<1>();
        __syncthreads();
        if (c + 2 < NCH)
            load_tile(tid, m0, n0w, smem_base, c + 2, s_nxt, Ahi, Alo, Wh, Wl);

        uint32_t abase  = smem_base + s_cur * GSTAGE;
        uint32_t a_warp = abase + wm * 64 * GROWB;
        uint32_t w_warp = abase + GATILE + wn * 64 * GROWB;

#pragma unroll
        for (int ka = 0; ka < 4; ka++) {
            uint32_t af[4][4];
#pragma unroll
            for (int mt = 0; mt < 4; mt++) {
                uint32_t addr = a_warp + (mt * 16 + a_row) * GROWB +
                                (ka * 16 + a_col) * 2;
                ldm_x4(af[mt][0], af[mt][1], af[mt][2], af[mt][3], addr);
            }
#pragma unroll
            for (int bi = 0; bi < 4; bi++) {
                uint32_t r0, r1, r2, r3;
                uint32_t addr = w_warp + (bi * 16 + b_row) * GROWB +
                                (ka * 16 + b_col) * 2;
                ldm_x4(r0, r1, r2, r3, addr);
#pragma unroll
                for (int mt = 0; mt < 4; mt++) {
                    mma_bf16(acc[mt][2 * bi],     af[mt][0], af[mt][1],
                             af[mt][2], af[mt][3], r0, r1);
                    mma_bf16(acc[mt][2 * bi + 1], af[mt][0], af[mt][1],
                             af[mt][2], af[mt][3], r2, r3);
                }
            }
        }
        s_cur = (s_cur == 2) ? 0 : s_cur + 1;
        s_nxt = (s_nxt == 2) ? 0 : s_nxt + 1;
    }

    // ---- epilogue ----
    const int r   = lid >> 2;
    const int cp2 = (lid & 3) * 2;
    __nv_bfloat16* hi_dst = (wsel == 0) ? Qh : (wsel == 1) ? Kh : Vh;
    __nv_bfloat16* lo_dst = (wsel == 0) ? Ql : (wsel == 1) ? Kl : Vl;
#pragma unroll
    for (int mt = 0; mt < 4; mt++) {
#pragma unroll
        for (int h2 = 0; h2 < 2; h2++) {
            int m = m0 + wm * 64 + mt * 16 + h2 * 8 + r;
            float v[16];
#pragma unroll
            for (int na = 0; na < 8; na++) {
                int nl = wn * 64 + na * 8 + cp2;
                v[2 * na]     = acc[mt][na][h2 * 2 + 0] + bias_s[nl];
                v[2 * na + 1] = acc[mt][na][h2 * 2 + 1] + bias_s[nl + 1];
            }
            if (!fused) {
#pragma unroll
                for (int na = 0; na < 8; na++) {
                    int n = n0w + wn * 64 + na * 8 + cp2;
                    *reinterpret_cast<float2*>(&Cout[(size_t)m * 1024 + n]) =
                        make_float2(v[2 * na], v[2 * na + 1]);
                }
            } else {
                int b  = m >> 11;
                int sq = m & (S_ - 1);
                if (wsel < 2) {
                    const float* cr = cosp + sq * HD_;
                    const float* sr = sinp + sq * HD_;
#pragma unroll
                    for (int na = 0; na < 4; na++) {
                        int hd = na * 8 + cp2;
                        float a0 = v[2 * na],     a1 = v[2 * na + 1];
                        float bb0 = v[2 * na + 8], bb1 = v[2 * na + 9];
                        v[2 * na]     = a0 * cr[hd]       - bb0 * sr[hd];
                        v[2 * na + 1] = a1 * cr[hd + 1]   - bb1 * sr[hd + 1];
                        v[2 * na + 8] = bb0 * cr[hd + 32] + a0 * sr[hd + 32];
                        v[2 * na + 9] = bb1 * cr[hd + 33] + a1 * sr[hd + 33];
                    }
                }
#pragma unroll
                for (int na = 0; na < 8; na++) {
                    int n  = n0w + wn * 64 + na * 8 + cp2;
                    int h  = n >> 6;
                    int hd = n & 63;
                    size_t off = ((size_t)(b * H_ + h) * S_ + sq) * HD_ + hd;
                    uint32_t hi, lo;
                    split2(v[2 * na], v[2 * na + 1], hi, lo);
                    *reinterpret_cast<uint32_t*>(&hi_dst[off]) = hi;
                    *reinterpret_cast<uint32_t*>(&lo_dst[off]) = lo;
                }
            }
        }
    }
}

// ---------------------------------------------------------------------------
// Flash attention, mma.sync bf16 3-term. Br=128 (8 warps), Bc=64,
// double-buffered K/V, 1 sync per tile.  (unchanged from R10)
// ---------------------------------------------------------------------------
#define AROWB 144
#define AQTILE (128 * AROWB)
#define AKTILE (64 * AROWB)
#define ASTAGE (4 * AKTILE)
#define ATT_DYN (2 * AQTILE + 2 * ASTAGE)

__device__ __forceinline__ void att_load_kv(
    int tid, uint32_t stage, int jt,
    const __nv_bfloat16* Khp, const __nv_bfloat16* Klp,
    const __nv_bfloat16* Vhp, const __nv_bfloat16* Vlp)
{
    int row = tid >> 2;
    int gb  = (tid & 3) * 2;
    size_t goff = (size_t)jt * 64 * HD_ + (size_t)row * HD_;
    const __nv_bfloat16* srcs[4] = { Khp + goff, Klp + goff, Vhp + goff, Vlp + goff };
#pragma unroll
    for (int t = 0; t < 4; t++) {
        uint32_t dbase = stage + t * AKTILE + row * AROWB;
#pragma unroll
        for (int g = 0; g < 2; g++)
            cp16(dbase + (gb + g) * 16, srcs[t] + (gb + g) * 8);
    }
    CP_COMMIT();
}

__global__ void __launch_bounds__(256) attn_tc(
    const __nv_bfloat16* __restrict__ Qhi, const __nv_bfloat16* __restrict__ Qlo,
    const __nv_bfloat16* __restrict__ Khi, const __nv_bfloat16* __restrict__ Klo,
    const __nv_bfloat16* __restrict__ Vhi, const __nv_bfloat16* __restrict__ Vlo,
    __nv_bfloat16* __restrict__ Ohi, __nv_bfloat16* __restrict__ Olo)
{
    extern __shared__ char dyn[];
    const int tid = threadIdx.x;
    const int wid = tid >> 5;
    const int lid = tid & 31;
    const int qt = blockIdx.x;
    const int bh = blockIdx.y;
    const int b  = bh >> 4;
    const int h  = bh & 15;

    uint32_t sQhi = smem_u32(dyn);
    uint32_t sQlo = sQhi + AQTILE;
    uint32_t sStg = sQlo + AQTILE;

    const size_t bh_off = (size_t)bh * S_ * HD_;
    const __nv_bfloat16* Qhp = Qhi + bh_off + (size_t)qt * 128 * HD_;
    const __nv_bfloat16* Qlp = Qlo + bh_off + (size_t)qt * 128 * HD_;
    const __nv_bfloat16* Khp = Khi + bh_off;
    const __nv_bfloat16* Klp = Klo + bh_off;
    const __nv_bfloat16* Vhp = Vhi + bh_off;
    const __nv_bfloat16* Vlp = Vlo + bh_off;

    {
        int row = tid >> 1;
        int gb  = (tid & 1) * 4;
#pragma unroll
        for (int g = 0; g < 4; g++) {
            cp16(sQhi + row * AROWB + (gb + g) * 16, Qhp + (size_t)row * HD_ + (gb + g) * 8);
            cp16(sQlo + row * AROWB + (gb + g) * 16, Qlp + (size_t)row * HD_ + (gb + g) * 8);
        }
        CP_COMMIT();
    }
    att_load_kv(tid, sStg, 0, Khp, Klp, Vhp, Vlp);
    cp_wait<0>();
    __syncthreads();

    const int a_row = ((lid >> 3) & 1) * 8 + (lid & 7);
    const int a_col = ((lid >> 4) & 1) * 8;
    uint32_t qh[4][4], ql[4][4];
#pragma unroll
    for (int t = 0; t < 4; t++) {
        uint32_t off = (wid * 16 + a_row) * AROWB + (t * 16 + a_col) * 2;
        ldm_x4(qh[t][0], qh[t][1], qh[t][2], qh[t][3], sQhi + off);
        ldm_x4(ql[t][0], ql[t][1], ql[t][2], ql[t][3], sQlo + off);
    }

    float m0 = -1e30f, m1 = -1e30f, l0 = 0.f, l1 = 0.f;
    float oacc[8][4];
#pragma unroll
    for (int n = 0; n < 8; n++)
#pragma unroll
        for (int v = 0; v < 4; v++) oacc[n][v] = 0.f;

    const int kbr = ((lid >> 4) & 1) * 8 + (lid & 7);
    const int kbc = ((lid >> 3) & 1) * 8;
    const int vbr = (lid & 7) + ((lid >> 3) & 1) * 8;
    const int vbc = ((lid >> 4) & 1) * 8;
    const int qrow_g = qt * 128 + wid * 16 + (lid >> 2);

    const int nt = 2 * qt + 2;
    for (int jt = 0; jt < nt; jt++) {
        if (jt > 0) {
            cp_wait<0>();
            __syncthreads();
        }
        if (jt + 1 < nt)
            att_load_kv(tid, sStg + ((jt + 1) & 1) * ASTAGE, jt + 1,
                        Khp, Klp, Vhp, Vlp);

        uint32_t sb   = sStg + (jt & 1) * ASTAGE;
        uint32_t skhi = sb;
        uint32_t sklo = sb + AKTILE;
        uint32_t svhi = sb + 2 * AKTILE;
        uint32_t svlo = sb + 3 * AKTILE;

        float sacc[8][4];
#pragma unroll
        for (int n = 0; n < 8; n++)
#pragma unroll
            for (int v = 0; v < 4; v++) sacc[n][v] = 0.f;

#pragma unroll
        for (int t = 0; t < 4; t++) {
#pragma unroll
            for (int g = 0; g < 4; g++) {
                uint32_t off = (g * 16 + kbr) * AROWB + (t * 16 + kbc) * 2;
                uint32_t b0, b1, b2, b3;
                ldm_x4(b0, b1, b2, b3, skhi + off);
                mma_bf16(sacc[2 * g],     qh[t][0], qh[t][1], qh[t][2], qh[t][3], b0, b1);
                mma_bf16(sacc[2 * g + 1], qh[t][0], qh[t][1], qh[t][2], qh[t][3], b2, b3);
                mma_bf16(sacc[2 * g],     ql[t][0], ql[t][1], ql[t][2], ql[t][3], b0, b1);
                mma_bf16(sacc[2 * g + 1], ql[t][0], ql[t][1], ql[t][2], ql[t][3], b2, b3);
                ldm_x4(b0, b1, b2, b3, sklo + off);
                mma_bf16(sacc[2 * g],     qh[t][0], qh[t][1], qh[t][2], qh[t][3], b0, b1);
                mma_bf16(sacc[2 * g + 1], qh[t][0], qh[t][1], qh[t][2], qh[t][3], b2, b3);
            }
        }

        const bool maybe_mask = (jt >= 2 * qt);
#pragma unroll
        for (int n = 0; n < 8; n++) {
#pragma unroll
            for (int v = 0; v < 4; v++) {
                float sv = sacc[n][v] * 0.125f;
                if (maybe_mask) {
                    int kg = jt * 64 + n * 8 + (lid & 3) * 2 + (v & 1);
                    int qg = qrow_g + ((v >= 2) ? 8 : 0);
                    if (kg > qg) sv = -1e30f;
                }
                sacc[n][v] = sv;
            }
        }

        float mx0 = -1e30f, mx1 = -1e30f;
#pragma unroll
        for (int n = 0; n < 8; n++) {
            mx0 = fmaxf(mx0, fmaxf(sacc[n][0], sacc[n][1]));
            mx1 = fmaxf(mx1, fmaxf(sacc[n][2], sacc[n][3]));
        }
        mx0 = fmaxf(mx0, __shfl_xor_sync(0xffffffff, mx0, 1));
        mx0 = fmaxf(mx0, __shfl_xor_sync(0xffffffff, mx0, 2));
        mx1 = fmaxf(mx1, __shfl_xor_sync(0xffffffff, mx1, 1));
        mx1 = fmaxf(mx1, __shfl_xor_sync(0xffffffff, mx1, 2));
        float mn0 = fmaxf(m0, mx0), mn1 = fmaxf(m1, mx1);
        float al0 = __expf(m0 - mn0), al1 = __expf(m1 - mn1);
        m0 = mn0; m1 = mn1;

        float s0 = 0.f, s1 = 0.f;
#pragma unroll
        for (int n = 0; n < 8; n++) {
            float p0 = __expf(sacc[n][0] - mn0);
            float p1 = __expf(sacc[n][1] - mn0);
            float p2 = __expf(sacc[n][2] - mn1);
            float p3 = __expf(sacc[n][3] - mn1);
            sacc[n][0] = p0; sacc[n][1] = p1; sacc[n][2] = p2; sacc[n][3] = p3;
            s0 += p0 + p1; s1 += p2 + p3;
        }
        s0 += __shfl_xor_sync(0xffffffff, s0, 1);
        s0 += __shfl_xor_sync(0xffffffff, s0, 2);
        s1 += __shfl_xor_sync(0xffffffff, s1, 1);
        s1 += __shfl_xor_sync(0xffffffff, s1, 2);
        l0 = l0 * al0 + s0;
        l1 = l1 * al1 + s1;
#pragma unroll
        for (int n = 0; n < 8; n++) {
            oacc[n][0] *= al0; oacc[n][1] *= al0;
            oacc[n][2] *= al1; oacc[n][3] *= al1;
        }

#pragma unroll
        for (int t = 0; t < 4; t++) {
            uint32_t ph[4], pl[4];
            split2(sacc[2 * t][0],     sacc[2 * t][1],     ph[0], pl[0]);
            split2(sacc[2 * t][2],     sacc[2 * t][3],     ph[1], pl[1]);
            split2(sacc[2 * t + 1][0], sacc[2 * t + 1][1], ph[2], pl[2]);
            split2(sacc[2 * t + 1][2], sacc[2 * t + 1][3], ph[3], pl[3]);
#pragma unroll
            for (int u = 0; u < 4; u++) {
                uint32_t off = (t * 16 + vbr) * AROWB + (u * 16 + vbc) * 2;
                uint32_t v0, v1, v2, v3;
                ldm_x4_t(v0, v1, v2, v3, svhi + off);
                mma_bf16(oacc[2 * u],     ph[0], ph[1], ph[2], ph[3], v0, v1);
                mma_bf16(oacc[2 * u + 1], ph[0], ph[1], ph[2], ph[3], v2, v3);
                mma_bf16(oacc[2 * u],     pl[0], pl[1], pl[2], pl[3], v0, v1);
                mma_bf16(oacc[2 * u + 1], pl[0], pl[1], pl[2], pl[3], v2, v3);
                ldm_x4_t(v0, v1, v2, v3, svlo + off);
                mma_bf16(oacc[2 * u],     ph[0], ph[1], ph[2], ph[3], v0, v1);
                mma_bf16(oacc[2 * u + 1], ph[0], ph[1], ph[2], ph[3], v2, v3);
            }
        }
    }

    float inv0 = 1.0f / l0, inv1 = 1.0f / l1;
    int srow = qt * 128 + wid * 16 + (lid >> 2);
    size_t base0 = ((size_t)b * S_ + srow) * D_ + h * HD_;
    size_t base1 = base0 + (size_t)8 * D_;
#pragma unroll
    for (int n = 0; n < 8; n++) {
        int c = n * 8 + (lid & 3) * 2;
        uint32_t hi, lo;
        split2(oacc[n][0] * inv0, oacc[n][1] * inv0, hi, lo);
        *reinterpret_cast<uint32_t*>(&Ohi[base0 + c]) = hi;
        *reinterpret_cast<uint32_t*>(&Olo[base0 + c]) = lo;
        split2(oacc[n][2] * inv1, oacc[n][3] * inv1, hi, lo);
        *reinterpret_cast<uint32_t*>(&Ohi[base1 + c]) = hi;
        *reinterpret_cast<uint32_t*>(&Olo[base1 + c]) = lo;
    }
}

// ---------------------------------------------------------------------------
// Launch
// ---------------------------------------------------------------------------
extern "C" void kernel_launch(void* const* d_in, const int* in_sizes, int n_in,
                              void* d_out, int out_size)
{
    const float* x    = (const float*)d_in[0];
    const float* cosp = (const float*)d_in[2];
    const float* sinp = (const float*)d_in[3];
    const float* Wq   = (const float*)d_in[4];
    const float* bq   = (const float*)d_in[5];
    const float* Wk   = (const float*)d_in[6];
    const float* bk   = (const float*)d_in[7];
    const float* Wv   = (const float*)d_in[8];
    const float* bv   = (const float*)d_in[9];
    const float* Wo   = (const float*)d_in[10];
    const float* bo   = (const float*)d_in[11];
    float* out        = (float*)d_out;

    __nv_bfloat16 *pxh, *pxl, *pWh, *pWl;
    __nv_bfloat16 *pQh, *pQl, *pKh, *pKl, *pVh, *pVl;
    cudaGetSymbolAddress((void**)&pxh, g_xhi);
    cudaGetSymbolAddress((void**)&pxl, g_xlo);
    cudaGetSymbolAddress((void**)&pWh, g_Whi);
    cudaGetSymbolAddress((void**)&pWl, g_Wlo);
    cudaGetSymbolAddress((void**)&pQh, g_Qhi);
    cudaGetSymbolAddress((void**)&pQl, g_Qlo);
    cudaGetSymbolAddress((void**)&pKh, g_Khi);
    cudaGetSymbolAddress((void**)&pKl, g_Klo);
    cudaGetSymbolAddress((void**)&pVh, g_Vhi);
    cudaGetSymbolAddress((void**)&pVl, g_Vlo);

    cudaFuncSetAttribute(gemm_tc, cudaFuncAttributeMaxDynamicSharedMemorySize,
                         GEMM_DYN_SMEM);
    cudaFuncSetAttribute(attn_tc, cudaFuncAttributeMaxDynamicSharedMemorySize,
                         ATT_DYN);

    const int DD = D_ * D_;

    // activation + weight splits
    split_kernel<<<(M_ * D_ / 4 + 255) / 256, 256>>>(x, pxh, pxl, M_ * D_ / 4);
    {
        dim3 wg((DD / 4 + 255) / 256, 4);
        wsplit_kernel<<<wg, 256>>>(Wq, Wk, Wv, Wo, pWh, pWl);
    }

    // fused QKV projection (RoPE+split for Q,K; split for V)
    {
        dim3 g(24, M_ / TM);     // (24, 32) = 768 CTAs
        gemm_tc<<<g, 256, GEMM_DYN_SMEM>>>(pxh, pxl, pWh, pWl,
                                           bq, bk, bv, nullptr,
                                           pQh, pQl, pKh, pKl, pVh, pVl,
                                           cosp, sinp, 1);
    }

    // attention (writes split ctx into g_xhi/g_xlo)
    {
        dim3 agrid(S_ / 128, B_ * H_);
        attn_tc<<<agrid, 256, ATT_DYN>>>(pQh, pQl, pKh, pKl, pVh, pVl, pxh, pxl);
    }

    // output projection -> d_out
    {
        dim3 g(8, M_ / TM);      // (8, 32) = 256 CTAs
        gemm_tc<<<g, 256, GEMM_DYN_SMEM>>>(pxh, pxl, pWh + 3 * DD, pWl + 3 * DD,
                                           bo, nullptr, nullptr, out,
                                           nullptr, nullptr, nullptr, nullptr,
                                           nullptr, nullptr,
                                           nullptr, nullptr, 0);
    }
}